// round 2
// baseline (speedup 1.0000x reference)
#include <cuda_runtime.h>
#include <cstdint>

// Scratch for the projected Q (=K=V) buffer: [B=4, S=2048, D=512] fp32.
__device__ float g_q[4 * 2048 * 512];

// ---------------------------------------------------------------------------
// Kernel 1: q = x @ Wq   (M=8192, K=512, N=512, all row-major fp32)
// 128x128 block tile, BK=8, 256 threads, 8x8 per-thread micro-tile.
// ---------------------------------------------------------------------------
#define GM 8192
#define GK 512
#define GN 512

__global__ __launch_bounds__(256) void gemm_proj(const float* __restrict__ X,
                                                 const float* __restrict__ W,
                                                 float* __restrict__ C) {
    __shared__ float Xs[8][128];  // transposed: Xs[k][m]
    __shared__ float Ws[8][128];  // Ws[k][n]

    const int tid = threadIdx.x;
    const int tx = tid & 15;       // 0..15 -> n micro-tile
    const int ty = tid >> 4;       // 0..15 -> m micro-tile
    const int m0 = blockIdx.y * 128;
    const int n0 = blockIdx.x * 128;

    float acc[8][8];
#pragma unroll
    for (int i = 0; i < 8; i++)
#pragma unroll
        for (int j = 0; j < 8; j++) acc[i][j] = 0.f;

    const int xr = tid >> 1;          // 0..127 (row in X tile)
    const int xk = (tid & 1) << 2;    // 0 or 4 (k offset, float4)
    const int wk = tid >> 5;          // 0..7
    const int wn = (tid & 31) << 2;   // 0..124

    for (int k0 = 0; k0 < GK; k0 += 8) {
        float4 xv = *(const float4*)(X + (size_t)(m0 + xr) * GK + k0 + xk);
        Xs[xk + 0][xr] = xv.x;
        Xs[xk + 1][xr] = xv.y;
        Xs[xk + 2][xr] = xv.z;
        Xs[xk + 3][xr] = xv.w;
        // FIX: include block column offset n0 (was missing -> rel_err 1.23)
        *(float4*)(&Ws[wk][wn]) =
            *(const float4*)(W + (size_t)(k0 + wk) * GN + n0 + wn);
        __syncthreads();

#pragma unroll
        for (int kk = 0; kk < 8; kk++) {
            float a[8], b[8];
            *(float4*)(a)     = *(float4*)&Xs[kk][ty * 8];
            *(float4*)(a + 4) = *(float4*)&Xs[kk][ty * 8 + 4];
            *(float4*)(b)     = *(float4*)&Ws[kk][tx * 8];
            *(float4*)(b + 4) = *(float4*)&Ws[kk][tx * 8 + 4];
#pragma unroll
            for (int i = 0; i < 8; i++)
#pragma unroll
                for (int j = 0; j < 8; j++) acc[i][j] = fmaf(a[i], b[j], acc[i][j]);
        }
        __syncthreads();
    }

    float* Cp = C + (size_t)(m0 + ty * 8) * GN + n0 + tx * 8;
#pragma unroll
    for (int i = 0; i < 8; i++) {
        *(float4*)(Cp + (size_t)i * GN) =
            make_float4(acc[i][0], acc[i][1], acc[i][2], acc[i][3]);
        *(float4*)(Cp + (size_t)i * GN + 4) =
            make_float4(acc[i][4], acc[i][5], acc[i][6], acc[i][7]);
    }
}

// ---------------------------------------------------------------------------
// Kernel 2: flash-attention, Q=K=V=g_q.
// Block = (b, h, 64-row q-tile). 256 threads as 16x16, 4x4 micro-tiles.
// Smem: Qs[64][64], KVs[64][64] (=V tile), Ss[64][64] (P), Kts[64][68] (K^T, padded).
// ---------------------------------------------------------------------------
constexpr int SEQ = 2048;
constexpr int HD  = 64;
constexpr int BT  = 64;         // kv tile rows
constexpr int KTS_LD = 68;      // padded leading dim for transposed K
constexpr int ATTN_SMEM_FLOATS = 64 * 64 * 3 + 64 * KTS_LD;  // 16640
constexpr int ATTN_SMEM_BYTES  = ATTN_SMEM_FLOATS * 4;       // 66560

__global__ __launch_bounds__(256) void attn_kernel(float* __restrict__ Out) {
    extern __shared__ float sm[];
    float* Qs  = sm;                  // [64][64]
    float* KVs = Qs + 64 * 64;        // [64][64]  (kv-row major: V layout)
    float* Ss  = KVs + 64 * 64;       // [64][64]  (P tile)
    float* Kts = Ss + 64 * 64;        // [64][68]  (K^T: [hd][kv])

    const int tid = threadIdx.x;
    const int tx = tid & 15;          // score col / hd col group
    const int ty = tid >> 4;          // score row group
    const int q0 = blockIdx.x * 64;
    const int h  = blockIdx.y;
    const int b  = blockIdx.z;

    const float* qb = g_q + ((size_t)b * SEQ) * 512 + h * HD;

    // Load Q tile [64][64] (coalesced float4)
    for (int idx = tid; idx < 64 * 16; idx += 256) {
        int r = idx >> 4, c = (idx & 15) << 2;
        *(float4*)&Qs[r * 64 + c] = *(const float4*)&qb[(size_t)(q0 + r) * 512 + c];
    }

    float m[4], l[4], o[4][4];
#pragma unroll
    for (int i = 0; i < 4; i++) {
        m[i] = -1e30f;
        l[i] = 0.f;
#pragma unroll
        for (int j = 0; j < 4; j++) o[i][j] = 0.f;
    }

    for (int t = 0; t < SEQ / BT; t++) {
        __syncthreads();  // prev-iter consumers of KVs/Ss/Kts done (also covers Q load)

        // Load KV tile [64][64]
        for (int idx = tid; idx < 64 * 16; idx += 256) {
            int r = idx >> 4, c = (idx & 15) << 2;
            *(float4*)&KVs[r * 64 + c] =
                *(const float4*)&qb[(size_t)(t * BT + r) * 512 + c];
        }
        __syncthreads();

        // Transpose into Kts[hd][kv] (padded -> conflict-free on both sides)
        for (int idx = tid; idx < 64 * 16; idx += 256) {
            int c = idx & 63;             // hd column
            int r4 = (idx >> 6) << 2;     // kv row group
            float4 v;
            v.x = KVs[(r4 + 0) * 64 + c];
            v.y = KVs[(r4 + 1) * 64 + c];
            v.z = KVs[(r4 + 2) * 64 + c];
            v.w = KVs[(r4 + 3) * 64 + c];
            *(float4*)&Kts[c * KTS_LD + r4] = v;
        }
        __syncthreads();

        // S = (Q @ K^T) * 0.125 ; rows ty*4+i, cols tx*4+j
        float sa[4][4];
#pragma unroll
        for (int i = 0; i < 4; i++)
#pragma unroll
            for (int j = 0; j < 4; j++) sa[i][j] = 0.f;

#pragma unroll
        for (int k = 0; k < HD; k += 4) {
            float4 qv[4], kv[4];
#pragma unroll
            for (int i = 0; i < 4; i++)
                qv[i] = *(float4*)&Qs[(ty * 4 + i) * 64 + k];
#pragma unroll
            for (int kk = 0; kk < 4; kk++)
                kv[kk] = *(float4*)&Kts[(k + kk) * KTS_LD + tx * 4];
#pragma unroll
            for (int i = 0; i < 4; i++) {
                sa[i][0] = fmaf(qv[i].x, kv[0].x, fmaf(qv[i].y, kv[1].x,
                           fmaf(qv[i].z, kv[2].x, fmaf(qv[i].w, kv[3].x, sa[i][0]))));
                sa[i][1] = fmaf(qv[i].x, kv[0].y, fmaf(qv[i].y, kv[1].y,
                           fmaf(qv[i].z, kv[2].y, fmaf(qv[i].w, kv[3].y, sa[i][1]))));
                sa[i][2] = fmaf(qv[i].x, kv[0].z, fmaf(qv[i].y, kv[1].z,
                           fmaf(qv[i].z, kv[2].z, fmaf(qv[i].w, kv[3].z, sa[i][2]))));
                sa[i][3] = fmaf(qv[i].x, kv[0].w, fmaf(qv[i].y, kv[1].w,
                           fmaf(qv[i].z, kv[2].w, fmaf(qv[i].w, kv[3].w, sa[i][3]))));
            }
        }

        // Online softmax per row (16 lanes share a row: shfl-xor over {8,4,2,1})
#pragma unroll
        for (int i = 0; i < 4; i++) {
            float mx = -1e30f;
#pragma unroll
            for (int j = 0; j < 4; j++) {
                sa[i][j] *= 0.125f;
                mx = fmaxf(mx, sa[i][j]);
            }
#pragma unroll
            for (int d = 8; d >= 1; d >>= 1)
                mx = fmaxf(mx, __shfl_xor_sync(0xffffffffu, mx, d));
            float mnew = fmaxf(m[i], mx);
            float alpha = __expf(m[i] - mnew);
            float rs = 0.f;
#pragma unroll
            for (int j = 0; j < 4; j++) {
                float p = __expf(sa[i][j] - mnew);
                sa[i][j] = p;
                rs += p;
            }
#pragma unroll
            for (int d = 8; d >= 1; d >>= 1)
                rs += __shfl_xor_sync(0xffffffffu, rs, d);
            l[i] = l[i] * alpha + rs;
            m[i] = mnew;
#pragma unroll
            for (int j = 0; j < 4; j++) o[i][j] *= alpha;
            *(float4*)&Ss[(ty * 4 + i) * 64 + tx * 4] =
                make_float4(sa[i][0], sa[i][1], sa[i][2], sa[i][3]);
        }
        __syncthreads();

        // O += P @ V ; rows ty*4+i, hd cols tx*4+j, V = KVs
#pragma unroll
        for (int k = 0; k < BT; k += 4) {
            float4 pv[4], vv[4];
#pragma unroll
            for (int i = 0; i < 4; i++)
                pv[i] = *(float4*)&Ss[(ty * 4 + i) * 64 + k];
#pragma unroll
            for (int kk = 0; kk < 4; kk++)
                vv[kk] = *(float4*)&KVs[(k + kk) * 64 + tx * 4];
#pragma unroll
            for (int i = 0; i < 4; i++) {
                o[i][0] = fmaf(pv[i].x, vv[0].x, fmaf(pv[i].y, vv[1].x,
                          fmaf(pv[i].z, vv[2].x, fmaf(pv[i].w, vv[3].x, o[i][0]))));
                o[i][1] = fmaf(pv[i].x, vv[0].y, fmaf(pv[i].y, vv[1].y,
                          fmaf(pv[i].z, vv[2].y, fmaf(pv[i].w, vv[3].y, o[i][1]))));
                o[i][2] = fmaf(pv[i].x, vv[0].z, fmaf(pv[i].y, vv[1].z,
                          fmaf(pv[i].z, vv[2].z, fmaf(pv[i].w, vv[3].z, o[i][2]))));
                o[i][3] = fmaf(pv[i].x, vv[0].w, fmaf(pv[i].y, vv[1].w,
                          fmaf(pv[i].z, vv[2].w, fmaf(pv[i].w, vv[3].w, o[i][3]))));
            }
        }
    }

    // Epilogue: normalize and write out[b, q0+row, h*64 + d]
    float* ob = Out + ((size_t)b * SEQ + q0) * 512 + h * HD;
#pragma unroll
    for (int i = 0; i < 4; i++) {
        float inv = 1.0f / l[i];
        *(float4*)&ob[(size_t)(ty * 4 + i) * 512 + tx * 4] =
            make_float4(o[i][0] * inv, o[i][1] * inv, o[i][2] * inv, o[i][3] * inv);
    }
}

// ---------------------------------------------------------------------------
extern "C" void kernel_launch(void* const* d_in, const int* in_sizes, int n_in,
                              void* d_out, int out_size) {
    const float* x  = (const float*)d_in[0];   // [4,2048,512]
    const float* Wq = (const float*)d_in[1];   // [512,512]
    float* out = (float*)d_out;

    float* qbuf = nullptr;
    cudaGetSymbolAddress((void**)&qbuf, g_q);

    // 1) projection GEMM
    dim3 ggrid(GN / 128, GM / 128);
    gemm_proj<<<ggrid, 256>>>(x, Wq, qbuf);

    // 2) attention
    cudaFuncSetAttribute(attn_kernel, cudaFuncAttributeMaxDynamicSharedMemorySize,
                         ATTN_SMEM_BYTES);
    dim3 agrid(SEQ / 64, 8, 4);
    attn_kernel<<<agrid, 256, ATTN_SMEM_BYTES>>>(out);
}